// round 14
// baseline (speedup 1.0000x reference)
#include <cuda_runtime.h>
#include <cuda_bf16.h>
#include <mma.h>
#include <cmath>
#include <cstdint>

using namespace nvcuda;
typedef __nv_bfloat16 bf16;

// Problem dims
constexpr int SEQ   = 2048;
constexpr int DE    = 2048;
constexpr int DMLP  = 8192;
constexpr int NH    = 16;

// Fused QKV layout (columns): [0,2048) q(h,e) | [2048,4096) k(h,e) |
// [4096,4111) v0 for heads 0..14 | 4111 pad | [4112,4240) v15 | pad to 4352
constexpr int NQKV   = 4352;
constexpr int VOFF0  = 4096;
constexpr int VOFF15 = 4112;
constexpr int YLD    = 160;   // ysmall padded K (143 real, rest zero)

// ---------------- device scratch (zero-initialized at module load) ----------
__device__ __align__(256) bf16  g_xn1b [SEQ*DE];
__device__ __align__(256) float g_packf[DE*NQKV];          // f32 staging
__device__ __align__(256) bf16  g_BqkvT[(size_t)NQKV*DE];  // N-major [NQKV][DE]
__device__ __align__(256) float g_bqkv [NQKV];
__device__ __align__(256) bf16  g_qkv  [SEQ*NQKV];
__device__ __align__(256) bf16  g_Sb   [(size_t)NH*SEQ*SEQ];  // bf16 scores
__device__ __align__(256) bf16  g_P    [SEQ*SEQ];
__device__ __align__(256) bf16  g_ys   [SEQ*YLD];          // cols 143..159 zero
__device__ __align__(256) bf16  g_WoT  [DE*YLD];           // N-major [DE][YLD]
__device__ __align__(256) float g_x2   [SEQ*DE];
__device__ __align__(256) bf16  g_xn2b [SEQ*DE];
__device__ __align__(256) float g_xn2f [SEQ*DE];
__device__ __align__(256) bf16  g_W1T  [(size_t)DMLP*DE];  // N-major [DMLP][DE]
__device__ __align__(256) bf16  g_h1   [(size_t)SEQ*DMLP];
__device__ __align__(256) bf16  g_W2T  [(size_t)DE*DMLP];  // N-major [DE][DMLP]

// ---------------- cp.async helpers ------------------------------------------
__device__ __forceinline__ void cp16(void* dst, const void* src) {
    unsigned d = (unsigned)__cvta_generic_to_shared(dst);
    asm volatile("cp.async.cg.shared.global [%0], [%1], 16;\n" :: "r"(d), "l"(src));
}
__device__ __forceinline__ void cp_commit() {
    asm volatile("cp.async.commit_group;\n");
}
template<int N> __device__ __forceinline__ void cp_wait() {
    asm volatile("cp.async.wait_group %0;\n" :: "n"(N));
}

// ---------------- big WMMA GEMM: 128x256 block, 64x64 warp tile -------------
// C(MxN) = epilogue( alpha * A(MxK) @ B(NxK)^T + bias ), per-z batch offsets.
// A row-major [M][K]; B N-major row-major [N][K] (col_major fragments).
// M mult of 128, N mult of 256, K mult of 32. 3-stage cp.async, 8 warps.
// MODE: 0 bf16 out (acc*alpha+bias) | 2 f32 out (2X+acc+bias)
//       3 bf16 out gelu(acc+bias)   | 4 f32 out (X+X2n+acc+bias)
constexpr int AS_STRIDE = 128 * 40;          // elems per A stage
constexpr int BS_STRIDE = 256 * 40;          // elems per B stage
constexpr int BIG_SMEM  = 3 * (AS_STRIDE + BS_STRIDE) * 2;   // 92160 B

template<int MODE>
__global__ __launch_bounds__(256, 1)
void big_gemm(int M, int N, int K,
              const bf16* __restrict__ A, int lda, long aB,
              const bf16* __restrict__ B, int ldb, long bB,
              void* __restrict__ C, int ldc, long cB,
              const float* __restrict__ bias, float alpha,
              const float* __restrict__ X, const float* __restrict__ X2n)
{
    extern __shared__ char sm[];
    bf16* As = (bf16*)sm;                          // [3][128][40]
    bf16* Bs = (bf16*)(sm + 3 * AS_STRIDE * 2);    // [3][256][40]

    const int tid    = threadIdx.x;
    const int warpId = tid >> 5;
    const int lane   = tid & 31;
    const int wm     = warpId & 1;    // 2 warps along M
    const int wn     = warpId >> 1;   // 4 warps along N
    const int bm     = blockIdx.y * 128;
    const int bn     = blockIdx.x * 256;
    const int z      = blockIdx.z;

    const bf16* Ag = A + (size_t)z * aB;
    const bf16* Bg = B + (size_t)z * bB;
    const size_t cOff = (size_t)z * cB;

    auto issue = [&](int kt, int s) {
        const int k0 = kt << 5;
        bf16* Asb = As + s * AS_STRIDE;
        bf16* Bsb = Bs + s * BS_STRIDE;
        #pragma unroll
        for (int it = 0; it < 2; it++) {           // A: 512 chunks of 16B
            int q = tid + it * 256;
            int r = q >> 2, c8 = q & 3;
            cp16(Asb + r * 40 + c8 * 8, Ag + (size_t)(bm + r) * lda + k0 + c8 * 8);
        }
        #pragma unroll
        for (int it = 0; it < 4; it++) {           // B: 1024 chunks of 16B
            int q = tid + it * 256;
            int r = q >> 2, c8 = q & 3;
            cp16(Bsb + r * 40 + c8 * 8, Bg + (size_t)(bn + r) * ldb + k0 + c8 * 8);
        }
        cp_commit();
    };

    wmma::fragment<wmma::accumulator,16,16,16,float> acc[4][4];
    #pragma unroll
    for (int i = 0; i < 4; i++)
        #pragma unroll
        for (int j = 0; j < 4; j++)
            wmma::fill_fragment(acc[i][j], 0.f);

    const int KT = K >> 5;
    issue(0, 0);
    if (KT > 1) issue(1, 1);

    for (int kt = 0; kt < KT; kt++) {
        if (kt + 1 < KT) cp_wait<1>(); else cp_wait<0>();
        __syncthreads();
        if (kt + 2 < KT) issue(kt + 2, (kt + 2) % 3);

        const int s = kt % 3;
        const bf16* Asb = As + s * AS_STRIDE;
        const bf16* Bsb = Bs + s * BS_STRIDE;
        #pragma unroll
        for (int ks = 0; ks < 32; ks += 16) {
            wmma::fragment<wmma::matrix_a,16,16,16,bf16,wmma::row_major> af[4];
            #pragma unroll
            for (int i = 0; i < 4; i++)
                wmma::load_matrix_sync(af[i], Asb + (wm*64 + i*16)*40 + ks, 40);
            #pragma unroll
            for (int j = 0; j < 4; j++) {
                wmma::fragment<wmma::matrix_b,16,16,16,bf16,wmma::col_major> bf;
                wmma::load_matrix_sync(bf, Bsb + (wn*64 + j*16)*40 + ks, 40);
                #pragma unroll
                for (int i = 0; i < 4; i++)
                    wmma::mma_sync(acc[i][j], af[i], bf, acc[i][j]);
            }
        }
    }
    __syncthreads();   // all warps done reading smem; reuse for epilogue stage

    float* stg = (float*)sm + warpId * 320;        // 16 x 20 per warp
    #pragma unroll
    for (int i = 0; i < 4; i++) {
        #pragma unroll
        for (int j = 0; j < 4; j++) {
            wmma::store_matrix_sync(stg, acc[i][j], 20, wmma::mem_row_major);
            __syncwarp();
            #pragma unroll
            for (int e = 0; e < 8; e++) {
                int el = lane*8 + e;
                int r = el >> 4, c = el & 15;
                float v = stg[r*20 + c] * alpha;
                int grow = bm + wm*64 + i*16 + r;
                int gcol = bn + wn*64 + j*16 + c;
                if (bias) v += bias[gcol];
                size_t idx = cOff + (size_t)grow * ldc + gcol;
                if constexpr (MODE == 0) {
                    ((bf16*)C)[idx] = __float2bfloat16(v);
                } else if constexpr (MODE == 2) {
                    ((float*)C)[idx] = 2.f * X[idx] + v;
                } else if constexpr (MODE == 3) {
                    float g = 0.5f * v *
                        (1.f + tanhf(0.7978845608028654f * (v + 0.044715f*v*v*v)));
                    ((bf16*)C)[idx] = __float2bfloat16(g);
                } else {
                    ((float*)C)[idx] = X[idx] + X2n[idx] + v;
                }
            }
            __syncwarp();
        }
    }
}

// ---------------- small WMMA GEMM (PV only: 128x128 block) ------------------
// C bf16 = A(MxK) @ B(KxN) + 0 ; B K-major.
__global__ __launch_bounds__(256)
void pv_gemm(int M, int N, int K,
             const bf16* __restrict__ A, int lda,
             const bf16* __restrict__ B, int ldb,
             bf16* __restrict__ C, int ldc)
{
    __shared__ __align__(16) bf16 As[2][128][40];
    __shared__ __align__(16) bf16 Bs[2][32][136];

    const int tid    = threadIdx.x;
    const int warpId = tid >> 5;
    const int lane   = tid & 31;
    const int wm     = warpId & 1;
    const int wn     = warpId >> 1;
    const int bm     = blockIdx.y * 128;
    const int bn     = blockIdx.x * 128;

    const int ar = tid >> 2,  ac = (tid & 3) * 8;
    const int ar2 = (tid + 256) >> 2, ac2 = ((tid + 256) & 3) * 8;
    const int br = tid >> 4,  bc = (tid & 15) * 8;
    const int br2 = (tid + 256) >> 4, bc2 = ((tid + 256) & 15) * 8;

    auto issue = [&](int kt, int buf) {
        const int k0 = kt << 5;
        cp16(&As[buf][ar ][ac ], A + (size_t)(bm + ar )*lda + k0 + ac );
        cp16(&As[buf][ar2][ac2], A + (size_t)(bm + ar2)*lda + k0 + ac2);
        cp16(&Bs[buf][br ][bc ], B + (size_t)(k0 + br )*ldb + bn + bc );
        cp16(&Bs[buf][br2][bc2], B + (size_t)(k0 + br2)*ldb + bn + bc2);
        cp_commit();
    };

    wmma::fragment<wmma::accumulator,16,16,16,float> acc[4][2];
    #pragma unroll
    for (int i = 0; i < 4; i++)
        #pragma unroll
        for (int j = 0; j < 2; j++)
            wmma::fill_fragment(acc[i][j], 0.f);

    const int ktiles = K >> 5;
    issue(0, 0);
    for (int kt = 0; kt < ktiles; kt++) {
        const int buf = kt & 1;
        if (kt + 1 < ktiles) { issue(kt + 1, buf ^ 1); cp_wait<1>(); }
        else                 { cp_wait<0>(); }
        __syncthreads();
        #pragma unroll
        for (int ks = 0; ks < 32; ks += 16) {
            wmma::fragment<wmma::matrix_a,16,16,16,bf16,wmma::row_major> af[4];
            wmma::fragment<wmma::matrix_b,16,16,16,bf16,wmma::row_major> bfr[2];
            #pragma unroll
            for (int i = 0; i < 4; i++)
                wmma::load_matrix_sync(af[i], &As[buf][wm*64 + i*16][ks], 40);
            #pragma unroll
            for (int j = 0; j < 2; j++)
                wmma::load_matrix_sync(bfr[j], &Bs[buf][ks][wn*32 + j*16], 136);
            #pragma unroll
            for (int i = 0; i < 4; i++)
                #pragma unroll
                for (int j = 0; j < 2; j++)
                    wmma::mma_sync(acc[i][j], af[i], bfr[j], acc[i][j]);
        }
        __syncthreads();
    }

    float* stg = ((float*)&As[0][0][0]) + warpId * 320;
    #pragma unroll
    for (int i = 0; i < 4; i++) {
        #pragma unroll
        for (int j = 0; j < 2; j++) {
            wmma::store_matrix_sync(stg, acc[i][j], 20, wmma::mem_row_major);
            __syncwarp();
            #pragma unroll
            for (int e = 0; e < 8; e++) {
                int el = lane*8 + e;
                int r = el >> 4, c = el & 15;
                float v = stg[r*20 + c];
                int grow = bm + wm*64 + i*16 + r;
                int gcol = bn + wn*32 + j*16 + c;
                C[(size_t)grow * ldc + gcol] = __float2bfloat16(v);
            }
            __syncwarp();
        }
    }
}

// ---------------- layernorm (population std) --------------------------------
template<bool WF>
__global__ __launch_bounds__(256)
void ln_kernel(const float* __restrict__ X, const float* __restrict__ gamma,
               const float* __restrict__ beta,
               bf16* __restrict__ ob, float* __restrict__ of)
{
    int row = blockIdx.x, tid = threadIdx.x;
    const float* xr = X + (size_t)row * DE;
    float v[8], s = 0.f, sq = 0.f;
    #pragma unroll
    for (int i = 0; i < 8; i++) {
        v[i] = xr[tid + i*256];
        s  += v[i];
        sq += v[i]*v[i];
    }
    __shared__ float r1[256], r2[256];
    r1[tid] = s; r2[tid] = sq; __syncthreads();
    for (int o = 128; o > 0; o >>= 1) {
        if (tid < o) { r1[tid] += r1[tid+o]; r2[tid] += r2[tid+o]; }
        __syncthreads();
    }
    float mean = r1[0] * (1.f/DE);
    float var  = r2[0] * (1.f/DE) - mean*mean;
    float sd   = sqrtf(fmaxf(var, 0.f));
    if (sd == 0.f) sd = 1.f;
    float rs = 1.f / sd;
    #pragma unroll
    for (int i = 0; i < 8; i++) {
        int d = tid + i*256;
        float y = gamma[d] * ((v[i] - mean) * rs) + beta[d];
        ob[(size_t)row*DE + d] = __float2bfloat16(y);
        if (WF) of[(size_t)row*DE + d] = y;
    }
}

// ---------------- batched softmax (bf16 scores) + per-head fold --------------
__global__ __launch_bounds__(256)
void softmax_kernel(const bf16* __restrict__ S, const bf16* __restrict__ qkv,
                    bf16* __restrict__ P, bf16* __restrict__ ys)
{
    int row = blockIdx.x, head = blockIdx.y, tid = threadIdx.x;
    const bf16* Sr = S + (size_t)head*SEQ*SEQ + (size_t)row*SEQ;
    float s[8];
    #pragma unroll
    for (int i = 0; i < 8; i++) s[i] = __bfloat162float(Sr[tid + i*256]);
    float mx = s[0];
    #pragma unroll
    for (int i = 1; i < 8; i++) mx = fmaxf(mx, s[i]);
    __shared__ float red[256];
    red[tid] = mx; __syncthreads();
    for (int o = 128; o > 0; o >>= 1) {
        if (tid < o) red[tid] = fmaxf(red[tid], red[tid+o]);
        __syncthreads();
    }
    mx = red[0]; __syncthreads();

    float e[8], ls = 0.f;
    #pragma unroll
    for (int i = 0; i < 8; i++) { e[i] = expf(s[i] - mx); ls += e[i]; }
    red[tid] = ls; __syncthreads();
    for (int o = 128; o > 0; o >>= 1) {
        if (tid < o) red[tid] += red[tid+o];
        __syncthreads();
    }
    float tot = red[0]; __syncthreads();

    if (head == 15) {
        float inv = 1.f / tot;
        #pragma unroll
        for (int i = 0; i < 8; i++)
            P[(size_t)row*SEQ + tid + i*256] = __float2bfloat16(e[i] * inv);
    } else {
        float dot = 0.f;
        #pragma unroll
        for (int i = 0; i < 8; i++) {
            int m = tid + i*256;
            dot += e[i] * __bfloat162float(qkv[(size_t)m*NQKV + VOFF0 + head]);
        }
        red[tid] = dot; __syncthreads();
        for (int o = 128; o > 0; o >>= 1) {
            if (tid < o) red[tid] += red[tid+o];
            __syncthreads();
        }
        if (tid == 0)
            ys[(size_t)row*YLD + head] = __float2bfloat16(red[0] / tot);
    }
}

// ---------------- packing / transpose ----------------------------------------
__global__ void pack_qkv_f32(const float* __restrict__ Wq,
                             const float* __restrict__ Wk,
                             const float* __restrict__ Wv,
                             float* __restrict__ out)
{
    const size_t total = (size_t)DE * NQKV;
    for (size_t idx = (size_t)blockIdx.x*blockDim.x + threadIdx.x;
         idx < total; idx += (size_t)gridDim.x*blockDim.x) {
        int d = (int)(idx / NQKV);
        int n = (int)(idx % NQKV);
        float w = 0.f;
        if (n < 2048) {
            w = Wq[(size_t)(n >> 7)*DE*128 + (size_t)d*128 + (n & 127)];
        } else if (n < 4096) {
            int m = n - 2048;
            w = Wk[(size_t)(m >> 7)*DE*128 + (size_t)d*128 + (m & 127)];
        } else if (n < 4111) {
            w = Wv[(size_t)(n - 4096)*DE*128 + (size_t)d*128];
        } else if (n >= VOFF15 && n < VOFF15 + 128) {
            w = Wv[(size_t)15*DE*128 + (size_t)d*128 + (n - VOFF15)];
        }
        out[idx] = w;
    }
}

// transpose + fp32->bf16: in [R][C] -> out [C][R]
__global__ void tcvt_kernel(const float* __restrict__ in, bf16* __restrict__ out,
                            int R, int C)
{
    __shared__ float t[32][33];
    int c0 = blockIdx.x * 32, r0 = blockIdx.y * 32;
    int x = threadIdx.x, y = threadIdx.y;
    #pragma unroll
    for (int j = 0; j < 32; j += 8)
        t[y + j][x] = in[(size_t)(r0 + y + j) * C + c0 + x];
    __syncthreads();
    #pragma unroll
    for (int j = 0; j < 32; j += 8)
        out[(size_t)(c0 + y + j) * R + r0 + x] = __float2bfloat16(t[x][y + j]);
}

__global__ void pack_bias_kernel(const float* __restrict__ bq,
                                 const float* __restrict__ bk,
                                 const float* __restrict__ bv,
                                 float* __restrict__ out)
{
    int n = blockIdx.x*blockDim.x + threadIdx.x;
    if (n >= NQKV) return;
    float b = 0.f;
    if (n < 2048)                           b = bq[n];
    else if (n < 4096)                      b = bk[n - 2048];
    else if (n < 4111)                      b = bv[(n - 4096)*128];
    else if (n >= VOFF15 && n < VOFF15+128) b = bv[15*128 + (n - VOFF15)];
    out[n] = b;
}

// WoT: N-major [DE][YLD]; WoT[n][k] = Wo[k][n] for k<143 else 0
__global__ void pack_woT_kernel(const float* __restrict__ Wo, bf16* __restrict__ out)
{
    for (int idx = blockIdx.x*blockDim.x + threadIdx.x;
         idx < DE*YLD; idx += gridDim.x*blockDim.x) {
        int n = idx / YLD, k = idx % YLD;
        out[idx] = __float2bfloat16(k < 143 ? Wo[(size_t)k*DE + n] : 0.f);
    }
}

// ---------------- host orchestration ----------------------------------------
extern "C" void kernel_launch(void* const* d_in, const int* in_sizes, int n_in,
                              void* d_out, int out_size)
{
    (void)in_sizes; (void)n_in; (void)out_size;
    const float* x   = (const float*)d_in[0];
    const float* Wq  = (const float*)d_in[1];
    const float* bq  = (const float*)d_in[2];
    const float* Wk  = (const float*)d_in[3];
    const float* bk  = (const float*)d_in[4];
    const float* Wv  = (const float*)d_in[5];
    const float* bv  = (const float*)d_in[6];
    const float* Wo  = (const float*)d_in[7];
    const float* bo  = (const float*)d_in[8];
    const float* g1  = (const float*)d_in[9];
    const float* be1 = (const float*)d_in[10];
    const float* g2  = (const float*)d_in[11];
    const float* be2 = (const float*)d_in[12];
    const float* W1  = (const float*)d_in[13];
    const float* b1  = (const float*)d_in[14];
    const float* W2  = (const float*)d_in[15];
    const float* b2  = (const float*)d_in[16];
    float* out = (float*)d_out;

    bf16 *xn1b, *BqkvT, *qkv, *Sb, *P, *ys, *WoT, *xn2b, *W1T, *h1, *W2T;
    float *packf, *bqkv, *x2, *xn2f;
    cudaGetSymbolAddress((void**)&xn1b,  g_xn1b);
    cudaGetSymbolAddress((void**)&packf, g_packf);
    cudaGetSymbolAddress((void**)&BqkvT, g_BqkvT);
    cudaGetSymbolAddress((void**)&bqkv,  g_bqkv);
    cudaGetSymbolAddress((void**)&qkv,   g_qkv);
    cudaGetSymbolAddress((void**)&Sb,    g_Sb);
    cudaGetSymbolAddress((void**)&P,     g_P);
    cudaGetSymbolAddress((void**)&ys,    g_ys);
    cudaGetSymbolAddress((void**)&WoT,   g_WoT);
    cudaGetSymbolAddress((void**)&x2,    g_x2);
    cudaGetSymbolAddress((void**)&xn2b,  g_xn2b);
    cudaGetSymbolAddress((void**)&xn2f,  g_xn2f);
    cudaGetSymbolAddress((void**)&W1T,   g_W1T);
    cudaGetSymbolAddress((void**)&h1,    g_h1);
    cudaGetSymbolAddress((void**)&W2T,   g_W2T);

    cudaFuncSetAttribute(big_gemm<0>, cudaFuncAttributeMaxDynamicSharedMemorySize, BIG_SMEM);
    cudaFuncSetAttribute(big_gemm<2>, cudaFuncAttributeMaxDynamicSharedMemorySize, BIG_SMEM);
    cudaFuncSetAttribute(big_gemm<3>, cudaFuncAttributeMaxDynamicSharedMemorySize, BIG_SMEM);
    cudaFuncSetAttribute(big_gemm<4>, cudaFuncAttributeMaxDynamicSharedMemorySize, BIG_SMEM);

    // Weight packing: QKV -> f32 staging -> transposed bf16 (N-major)
    pack_qkv_f32    <<<4096, 256>>>(Wq, Wk, Wv, packf);
    pack_bias_kernel<<<(NQKV + 255)/256, 256>>>(bq, bk, bv, bqkv);
    pack_woT_kernel <<<640, 256>>>(Wo, WoT);
    dim3 tb(32, 8);
    tcvt_kernel<<<dim3(NQKV/32, DE/32),  tb>>>(packf, BqkvT, DE,   NQKV);
    tcvt_kernel<<<dim3(DMLP/32, DE/32),  tb>>>(W1,    W1T,   DE,   DMLP);
    tcvt_kernel<<<dim3(DE/32,  DMLP/32), tb>>>(W2,    W2T,   DMLP, DE);

    // LN1
    ln_kernel<false><<<SEQ, 256>>>(x, g1, be1, xn1b, nullptr);

    // Fused QKV: qkv = xn1 @ Wqkv + bias   (2048 x 4352, K=2048)
    big_gemm<0><<<dim3(NQKV/256, SEQ/128), 256, BIG_SMEM>>>(
        SEQ, NQKV, DE, xn1b, DE, 0, BqkvT, DE, 0, qkv, NQKV, 0,
        bqkv, 1.f, nullptr, nullptr);

    // Batched scores: S[h] = q_h k_h^T / sqrt(128)  -> bf16
    const float alphaS = 0.08838834764831845f;
    big_gemm<0><<<dim3(SEQ/256, SEQ/128, NH), 256, BIG_SMEM>>>(
        SEQ, SEQ, 128, qkv, NQKV, 128, qkv + 2048, NQKV, 128,
        Sb, SEQ, (long)SEQ*SEQ, nullptr, alphaS, nullptr, nullptr);

    // Batched softmax: heads 0..14 fold to scalar, head 15 writes P
    softmax_kernel<<<dim3(SEQ, NH), 256>>>(Sb, qkv, P, ys);

    // Head 15 PV: P @ v15 -> ysmall cols [15,143)
    pv_gemm<<<dim3(1, SEQ/128), 256>>>(
        SEQ, 128, SEQ, P, SEQ, qkv + VOFF15, NQKV, ys + 15, YLD);

    // mh + residual: x2 = 2x + ysmall @ Wo_top + bo  (K padded to 160)
    big_gemm<2><<<dim3(DE/256, SEQ/128), 256, BIG_SMEM>>>(
        SEQ, DE, YLD, ys, YLD, 0, WoT, YLD, 0, x2, DE, 0,
        bo, 1.f, x, nullptr);

    // LN2
    ln_kernel<true><<<SEQ, 256>>>(x2, g2, be2, xn2b, xn2f);

    // MLP1: gelu(xn2 @ W1 + b1) -> bf16
    big_gemm<3><<<dim3(DMLP/256, SEQ/128), 256, BIG_SMEM>>>(
        SEQ, DMLP, DE, xn2b, DE, 0, W1T, DE, 0, h1, DMLP, 0,
        b1, 1.f, nullptr, nullptr);

    // MLP2 + final residual: out = x2 + xn2 + h1 @ W2 + b2
    big_gemm<4><<<dim3(DE/256, SEQ/128), 256, BIG_SMEM>>>(
        SEQ, DE, DMLP, h1, DMLP, 0, W2T, DMLP, 0, out, DE, 0,
        b2, 1.f, x2, xn2f);
}

// round 15
// speedup vs baseline: 1.0688x; 1.0688x over previous
#include <cuda_runtime.h>
#include <cuda_bf16.h>
#include <mma.h>
#include <cmath>
#include <cstdint>

using namespace nvcuda;
typedef __nv_bfloat16 bf16;

// Problem dims
constexpr int SEQ   = 2048;
constexpr int DE    = 2048;
constexpr int DMLP  = 8192;
constexpr int NH    = 16;

// Fused QKV layout (columns): [0,2048) q(h,e) | [2048,4096) k(h,e) |
// [4096,4111) v0 for heads 0..14 | 4111 pad | [4112,4240) v15 | pad to 4352
constexpr int NQKV   = 4352;
constexpr int VOFF0  = 4096;
constexpr int VOFF15 = 4112;
constexpr int YLD    = 160;   // ysmall padded K (143 real, rest zero)

// ---------------- device scratch (zero-initialized at module load) ----------
__device__ __align__(256) bf16  g_xn1b [SEQ*DE];
__device__ __align__(256) bf16  g_Bqkv [DE*NQKV];          // K-major [DE][NQKV]
__device__ __align__(256) float g_bqkv [NQKV];
__device__ __align__(256) bf16  g_qkv  [SEQ*NQKV];
__device__ __align__(256) bf16  g_Sb   [(size_t)NH*SEQ*SEQ];  // bf16 scores
__device__ __align__(256) bf16  g_P    [SEQ*SEQ];
__device__ __align__(256) bf16  g_ys   [SEQ*YLD];          // cols 143..159 zero
__device__ __align__(256) bf16  g_Wob  [YLD*DE];           // K-major, rows 143+ zero
__device__ __align__(256) float g_x2   [SEQ*DE];
__device__ __align__(256) bf16  g_xn2b [SEQ*DE];
__device__ __align__(256) float g_xn2f [SEQ*DE];
__device__ __align__(256) bf16  g_W1b  [(size_t)DE*DMLP];  // K-major
__device__ __align__(256) bf16  g_h1   [(size_t)SEQ*DMLP];
__device__ __align__(256) bf16  g_W2b  [(size_t)DMLP*DE];  // K-major

// ---------------- cp.async helpers ------------------------------------------
__device__ __forceinline__ void cp16(void* dst, const void* src) {
    unsigned d = (unsigned)__cvta_generic_to_shared(dst);
    asm volatile("cp.async.cg.shared.global [%0], [%1], 16;\n" :: "r"(d), "l"(src));
}
__device__ __forceinline__ void cp_commit() {
    asm volatile("cp.async.commit_group;\n");
}
template<int N> __device__ __forceinline__ void cp_wait() {
    asm volatile("cp.async.wait_group %0;\n" :: "n"(N));
}

// ---------------- WMMA bf16 GEMM, 4-stage cp.async, 1 sync per k-tile -------
// C(MxN) = epilogue( alpha * A(MxK) @ B + bias ), per-z batch offsets.
// TRANSB=0: B is K-major [K][N] (row_major frags). TRANSB=1: B is N-major
// [N][K] (col_major frags) => computes A @ B^T.
// Block 128x128, warp tile 64x32, 8 warps, 2 CTAs/SM.
// MODE: 0 bf16 out (acc*alpha+bias) | 2 f32 out (2X+acc+bias)
//       3 bf16 out gelu(acc+bias)   | 4 f32 out (X+X2n+acc+bias)
template<int MODE, bool TRANSB>
__global__ __launch_bounds__(256, 2)
void gemm_kernel(int M, int N, int K,
                 const bf16* __restrict__ A, int lda, long aB,
                 const bf16* __restrict__ B, int ldb, long bB,
                 void* __restrict__ C, int ldc, long cB,
                 const float* __restrict__ bias, float alpha,
                 const float* __restrict__ X, const float* __restrict__ X2n)
{
    constexpr int ASZ   = 128 * 40;                    // 5120 elems
    constexpr int BSZ   = TRANSB ? 128 * 40 : 32 * 136;
    constexpr int STAGE = ASZ + BSZ;
    constexpr int BSTR  = TRANSB ? 40 : 136;           // B smem row stride

    extern __shared__ char smc[];
    bf16* base = (bf16*)smc;

    const int tid    = threadIdx.x;
    const int warpId = tid >> 5;
    const int lane   = tid & 31;
    const int wm     = warpId & 1;    // 2 warps along M
    const int wn     = warpId >> 1;   // 4 warps along N
    const int bm     = blockIdx.y * 128;
    const int bn     = blockIdx.x * 128;
    const int z      = blockIdx.z;

    const bf16* Ag = A + (size_t)z * aB;
    const bf16* Bg = B + (size_t)z * bB;
    const size_t cOff = (size_t)z * cB;

    // chunk maps (16B each; 2 per thread per operand tile)
    const int ar  = tid >> 2,        ac  = (tid & 3) * 8;          // A rows 0..63
    const int ar2 = (tid + 256) >> 2, ac2 = ((tid + 256) & 3) * 8; // A rows 64..127
    const int br  = tid >> 4,        bc  = (tid & 15) * 8;         // B(kmaj) rows 0..15
    const int br2 = (tid + 256) >> 4, bc2 = ((tid + 256) & 15) * 8;

    auto issue = [&](int kt, int s) {
        const int k0 = kt << 5;
        bf16* Asb = base + s * STAGE;
        bf16* Bsb = Asb + ASZ;
        cp16(Asb + ar  * 40 + ac,  Ag + (size_t)(bm + ar ) * lda + k0 + ac );
        cp16(Asb + ar2 * 40 + ac2, Ag + (size_t)(bm + ar2) * lda + k0 + ac2);
        if (TRANSB) {
            cp16(Bsb + ar  * 40 + ac,  Bg + (size_t)(bn + ar ) * ldb + k0 + ac );
            cp16(Bsb + ar2 * 40 + ac2, Bg + (size_t)(bn + ar2) * ldb + k0 + ac2);
        } else {
            cp16(Bsb + br  * 136 + bc,  Bg + (size_t)(k0 + br ) * ldb + bn + bc );
            cp16(Bsb + br2 * 136 + bc2, Bg + (size_t)(k0 + br2) * ldb + bn + bc2);
        }
        cp_commit();
    };

    wmma::fragment<wmma::accumulator,16,16,16,float> acc[4][2];
    #pragma unroll
    for (int i = 0; i < 4; i++)
        #pragma unroll
        for (int j = 0; j < 2; j++)
            wmma::fill_fragment(acc[i][j], 0.f);

    const int KT = K >> 5;
    // prologue: 3 tiles in flight
    #pragma unroll
    for (int i = 0; i < 3; i++) {
        if (i < KT) issue(i, i); else cp_commit();
    }

    for (int kt = 0; kt < KT; kt++) {
        cp_wait<2>();          // with constant 3 groups outstanding, tile kt is done
        __syncthreads();       // make tile kt visible; all warps done with kt-1
        if (kt + 3 < KT) issue(kt + 3, (kt + 3) & 3);
        else             cp_commit();   // keep group count constant

        const int s = kt & 3;
        const bf16* Asb = base + s * STAGE;
        const bf16* Bsb = Asb + ASZ;
        #pragma unroll
        for (int ks = 0; ks < 32; ks += 16) {
            wmma::fragment<wmma::matrix_a,16,16,16,bf16,wmma::row_major> af[4];
            #pragma unroll
            for (int i = 0; i < 4; i++)
                wmma::load_matrix_sync(af[i], Asb + (wm*64 + i*16)*40 + ks, 40);
            if (TRANSB) {
                wmma::fragment<wmma::matrix_b,16,16,16,bf16,wmma::col_major> bfr[2];
                #pragma unroll
                for (int j = 0; j < 2; j++)
                    wmma::load_matrix_sync(bfr[j], Bsb + (wn*32 + j*16)*BSTR + ks, BSTR);
                #pragma unroll
                for (int i = 0; i < 4; i++)
                    #pragma unroll
                    for (int j = 0; j < 2; j++)
                        wmma::mma_sync(acc[i][j], af[i], bfr[j], acc[i][j]);
            } else {
                wmma::fragment<wmma::matrix_b,16,16,16,bf16,wmma::row_major> bfr[2];
                #pragma unroll
                for (int j = 0; j < 2; j++)
                    wmma::load_matrix_sync(bfr[j], Bsb + ks*BSTR + wn*32 + j*16, BSTR);
                #pragma unroll
                for (int i = 0; i < 4; i++)
                    #pragma unroll
                    for (int j = 0; j < 2; j++)
                        wmma::mma_sync(acc[i][j], af[i], bfr[j], acc[i][j]);
            }
        }
    }
    __syncthreads();   // all warps done with smem; reuse front as epilogue stage

    float* stg = (float*)smc + warpId * 320;     // 16 x 20 per warp
    #pragma unroll
    for (int i = 0; i < 4; i++) {
        #pragma unroll
        for (int j = 0; j < 2; j++) {
            wmma::store_matrix_sync(stg, acc[i][j], 20, wmma::mem_row_major);
            __syncwarp();
            #pragma unroll
            for (int e = 0; e < 8; e++) {
                int el = lane*8 + e;
                int r = el >> 4, c = el & 15;
                float v = stg[r*20 + c] * alpha;
                int grow = bm + wm*64 + i*16 + r;
                int gcol = bn + wn*32 + j*16 + c;
                if (bias) v += bias[gcol];
                size_t idx = cOff + (size_t)grow * ldc + gcol;
                if constexpr (MODE == 0) {
                    ((bf16*)C)[idx] = __float2bfloat16(v);
                } else if constexpr (MODE == 2) {
                    ((float*)C)[idx] = 2.f * X[idx] + v;
                } else if constexpr (MODE == 3) {
                    float g = 0.5f * v *
                        (1.f + tanhf(0.7978845608028654f * (v + 0.044715f*v*v*v)));
                    ((bf16*)C)[idx] = __float2bfloat16(g);
                } else {
                    ((float*)C)[idx] = X[idx] + X2n[idx] + v;
                }
            }
            __syncwarp();
        }
    }
}

constexpr int SMEM_NT = 4 * (128*40 + 32*136) * 2;   // 75776 B (K-major B)
constexpr int SMEM_TR = 4 * (128*40 + 128*40) * 2;   // 81920 B (N-major B)

// ---------------- layernorm (population std) --------------------------------
template<bool WF>
__global__ __launch_bounds__(256)
void ln_kernel(const float* __restrict__ X, const float* __restrict__ gamma,
               const float* __restrict__ beta,
               bf16* __restrict__ ob, float* __restrict__ of)
{
    int row = blockIdx.x, tid = threadIdx.x;
    const float* xr = X + (size_t)row * DE;
    float v[8], s = 0.f, sq = 0.f;
    #pragma unroll
    for (int i = 0; i < 8; i++) {
        v[i] = xr[tid + i*256];
        s  += v[i];
        sq += v[i]*v[i];
    }
    __shared__ float r1[256], r2[256];
    r1[tid] = s; r2[tid] = sq; __syncthreads();
    for (int o = 128; o > 0; o >>= 1) {
        if (tid < o) { r1[tid] += r1[tid+o]; r2[tid] += r2[tid+o]; }
        __syncthreads();
    }
    float mean = r1[0] * (1.f/DE);
    float var  = r2[0] * (1.f/DE) - mean*mean;
    float sd   = sqrtf(fmaxf(var, 0.f));
    if (sd == 0.f) sd = 1.f;
    float rs = 1.f / sd;
    #pragma unroll
    for (int i = 0; i < 8; i++) {
        int d = tid + i*256;
        float y = gamma[d] * ((v[i] - mean) * rs) + beta[d];
        ob[(size_t)row*DE + d] = __float2bfloat16(y);
        if (WF) of[(size_t)row*DE + d] = y;
    }
}

// ---------------- batched softmax (bf16 scores) + per-head fold --------------
__global__ __launch_bounds__(256)
void softmax_kernel(const bf16* __restrict__ S, const bf16* __restrict__ qkv,
                    bf16* __restrict__ P, bf16* __restrict__ ys)
{
    int row = blockIdx.x, head = blockIdx.y, tid = threadIdx.x;
    const bf16* Sr = S + (size_t)head*SEQ*SEQ + (size_t)row*SEQ;
    float s[8];
    #pragma unroll
    for (int i = 0; i < 8; i++) s[i] = __bfloat162float(Sr[tid + i*256]);
    float mx = s[0];
    #pragma unroll
    for (int i = 1; i < 8; i++) mx = fmaxf(mx, s[i]);
    __shared__ float red[256];
    red[tid] = mx; __syncthreads();
    for (int o = 128; o > 0; o >>= 1) {
        if (tid < o) red[tid] = fmaxf(red[tid], red[tid+o]);
        __syncthreads();
    }
    mx = red[0]; __syncthreads();

    float e[8], ls = 0.f;
    #pragma unroll
    for (int i = 0; i < 8; i++) { e[i] = expf(s[i] - mx); ls += e[i]; }
    red[tid] = ls; __syncthreads();
    for (int o = 128; o > 0; o >>= 1) {
        if (tid < o) red[tid] += red[tid+o];
        __syncthreads();
    }
    float tot = red[0]; __syncthreads();

    if (head == 15) {
        float inv = 1.f / tot;
        #pragma unroll
        for (int i = 0; i < 8; i++)
            P[(size_t)row*SEQ + tid + i*256] = __float2bfloat16(e[i] * inv);
    } else {
        float dot = 0.f;
        #pragma unroll
        for (int i = 0; i < 8; i++) {
            int m = tid + i*256;
            dot += e[i] * __bfloat162float(qkv[(size_t)m*NQKV + VOFF0 + head]);
        }
        red[tid] = dot; __syncthreads();
        for (int o = 128; o > 0; o >>= 1) {
            if (tid < o) red[tid] += red[tid+o];
            __syncthreads();
        }
        if (tid == 0)
            ys[(size_t)row*YLD + head] = __float2bfloat16(red[0] / tot);
    }
}

// ---------------- weight packing --------------------------------------------
__global__ void pack_qkv_kernel(const float* __restrict__ Wq,
                                const float* __restrict__ Wk,
                                const float* __restrict__ Wv,
                                bf16* __restrict__ Bq)
{
    const size_t total = (size_t)DE * NQKV;
    for (size_t idx = (size_t)blockIdx.x*blockDim.x + threadIdx.x;
         idx < total; idx += (size_t)gridDim.x*blockDim.x) {
        int d = (int)(idx / NQKV);
        int n = (int)(idx % NQKV);
        float w = 0.f;
        if (n < 2048) {
            w = Wq[(size_t)(n >> 7)*DE*128 + (size_t)d*128 + (n & 127)];
        } else if (n < 4096) {
            int m = n - 2048;
            w = Wk[(size_t)(m >> 7)*DE*128 + (size_t)d*128 + (m & 127)];
        } else if (n < 4111) {
            w = Wv[(size_t)(n - 4096)*DE*128 + (size_t)d*128];
        } else if (n >= VOFF15 && n < VOFF15 + 128) {
            w = Wv[(size_t)15*DE*128 + (size_t)d*128 + (n - VOFF15)];
        }
        Bq[idx] = __float2bfloat16(w);
    }
}

__global__ void pack_bias_kernel(const float* __restrict__ bq,
                                 const float* __restrict__ bk,
                                 const float* __restrict__ bv,
                                 float* __restrict__ out)
{
    int n = blockIdx.x*blockDim.x + threadIdx.x;
    if (n >= NQKV) return;
    float b = 0.f;
    if (n < 2048)                           b = bq[n];
    else if (n < 4096)                      b = bk[n - 2048];
    else if (n < 4111)                      b = bv[(n - 4096)*128];
    else if (n >= VOFF15 && n < VOFF15+128) b = bv[15*128 + (n - VOFF15)];
    out[n] = b;
}

__global__ void pack_wo_kernel(const float* __restrict__ Wo, bf16* __restrict__ out)
{
    for (int idx = blockIdx.x*blockDim.x + threadIdx.x;
         idx < YLD*DE; idx += gridDim.x*blockDim.x) {
        int r = idx / DE;
        out[idx] = __float2bfloat16(r < 143 ? Wo[idx] : 0.f);
    }
}

// vectorized fp32 -> bf16
__global__ void cvt_kernel(const float4* __restrict__ in, uint2* __restrict__ out,
                           size_t n4)
{
    for (size_t i = (size_t)blockIdx.x*blockDim.x + threadIdx.x;
         i < n4; i += (size_t)gridDim.x*blockDim.x) {
        float4 v = in[i];
        __nv_bfloat162 a = __floats2bfloat162_rn(v.x, v.y);
        __nv_bfloat162 b = __floats2bfloat162_rn(v.z, v.w);
        uint2 o;
        o.x = *(unsigned*)&a;
        o.y = *(unsigned*)&b;
        out[i] = o;
    }
}

// ---------------- host orchestration ----------------------------------------
extern "C" void kernel_launch(void* const* d_in, const int* in_sizes, int n_in,
                              void* d_out, int out_size)
{
    (void)in_sizes; (void)n_in; (void)out_size;
    const float* x   = (const float*)d_in[0];
    const float* Wq  = (const float*)d_in[1];
    const float* bq  = (const float*)d_in[2];
    const float* Wk  = (const float*)d_in[3];
    const float* bk  = (const float*)d_in[4];
    const float* Wv  = (const float*)d_in[5];
    const float* bv  = (const float*)d_in[6];
    const float* Wo  = (const float*)d_in[7];
    const float* bo  = (const float*)d_in[8];
    const float* g1  = (const float*)d_in[9];
    const float* be1 = (const float*)d_in[10];
    const float* g2  = (const float*)d_in[11];
    const float* be2 = (const float*)d_in[12];
    const float* W1  = (const float*)d_in[13];
    const float* b1  = (const float*)d_in[14];
    const float* W2  = (const float*)d_in[15];
    const float* b2  = (const float*)d_in[16];
    float* out = (float*)d_out;

    bf16 *xn1b, *Bqkv, *qkv, *Sb, *P, *ys, *Wob, *xn2b, *W1b, *h1, *W2b;
    float *bqkv, *x2, *xn2f;
    cudaGetSymbolAddress((void**)&xn1b, g_xn1b);
    cudaGetSymbolAddress((void**)&Bqkv, g_Bqkv);
    cudaGetSymbolAddress((void**)&bqkv, g_bqkv);
    cudaGetSymbolAddress((void**)&qkv,  g_qkv);
    cudaGetSymbolAddress((void**)&Sb,   g_Sb);
    cudaGetSymbolAddress((void**)&P,    g_P);
    cudaGetSymbolAddress((void**)&ys,   g_ys);
    cudaGetSymbolAddress((void**)&Wob,  g_Wob);
    cudaGetSymbolAddress((void**)&x2,   g_x2);
    cudaGetSymbolAddress((void**)&xn2b, g_xn2b);
    cudaGetSymbolAddress((void**)&xn2f, g_xn2f);
    cudaGetSymbolAddress((void**)&W1b,  g_W1b);
    cudaGetSymbolAddress((void**)&h1,   g_h1);
    cudaGetSymbolAddress((void**)&W2b,  g_W2b);

    cudaFuncSetAttribute(gemm_kernel<0,false>,
        cudaFuncAttributeMaxDynamicSharedMemorySize, SMEM_NT);
    cudaFuncSetAttribute(gemm_kernel<0,true>,
        cudaFuncAttributeMaxDynamicSharedMemorySize, SMEM_TR);
    cudaFuncSetAttribute(gemm_kernel<2,false>,
        cudaFuncAttributeMaxDynamicSharedMemorySize, SMEM_NT);
    cudaFuncSetAttribute(gemm_kernel<3,false>,
        cudaFuncAttributeMaxDynamicSharedMemorySize, SMEM_NT);
    cudaFuncSetAttribute(gemm_kernel<4,false>,
        cudaFuncAttributeMaxDynamicSharedMemorySize, SMEM_NT);

    // Weight packing / conversion (K-major everywhere)
    pack_qkv_kernel <<<4096, 256>>>(Wq, Wk, Wv, Bqkv);
    pack_bias_kernel<<<(NQKV + 255)/256, 256>>>(bq, bk, bv, bqkv);
    pack_wo_kernel  <<<640, 256>>>(Wo, Wob);
    cvt_kernel      <<<4096, 256>>>((const float4*)W1, (uint2*)W1b,
                                    (size_t)DE * DMLP / 4);
    cvt_kernel      <<<4096, 256>>>((const float4*)W2, (uint2*)W2b,
                                    (size_t)DMLP * DE / 4);

    // LN1
    ln_kernel<false><<<SEQ, 256>>>(x, g1, be1, xn1b, nullptr);

    // Fused QKV: qkv = xn1 @ Wqkv + bias   (2048 x 4352, K=2048)
    gemm_kernel<0,false><<<dim3(NQKV/128, SEQ/128), 256, SMEM_NT>>>(
        SEQ, NQKV, DE, xn1b, DE, 0, Bqkv, NQKV, 0, qkv, NQKV, 0,
        bqkv, 1.f, nullptr, nullptr);

    // Batched scores: S[h] = q_h k_h^T / sqrt(128) -> bf16  (z = head)
    const float alphaS = 0.08838834764831845f;
    gemm_kernel<0,true><<<dim3(SEQ/128, SEQ/128, NH), 256, SMEM_TR>>>(
        SEQ, SEQ, 128, qkv, NQKV, 128, qkv + 2048, NQKV, 128,
        Sb, SEQ, (long)SEQ*SEQ, nullptr, alphaS, nullptr, nullptr);

    // Batched softmax: heads 0..14 fold to scalar, head 15 writes P
    softmax_kernel<<<dim3(SEQ, NH), 256>>>(Sb, qkv, P, ys);

    // Head 15 PV: P @ v15 -> ysmall cols [15,143)
    gemm_kernel<0,false><<<dim3(1, SEQ/128), 256, SMEM_NT>>>(
        SEQ, 128, SEQ, P, SEQ, 0, qkv + VOFF15, NQKV, 0,
        ys + 15, YLD, 0, nullptr, 1.f, nullptr, nullptr);

    // mh + residual: x2 = 2x + ysmall @ Wo_top + bo  (K padded to 160)
    gemm_kernel<2,false><<<dim3(DE/128, SEQ/128), 256, SMEM_NT>>>(
        SEQ, DE, YLD, ys, YLD, 0, Wob, DE, 0, x2, DE, 0,
        bo, 1.f, x, nullptr);

    // LN2
    ln_kernel<true><<<SEQ, 256>>>(x2, g2, be2, xn2b, xn2f);

    // MLP1: gelu(xn2 @ W1 + b1) -> bf16
    gemm_kernel<3,false><<<dim3(DMLP/128, SEQ/128), 256, SMEM_NT>>>(
        SEQ, DMLP, DE, xn2b, DE, 0, W1b, DMLP, 0, h1, DMLP, 0,
        b1, 1.f, nullptr, nullptr);

    // MLP2 + final residual: out = x2 + xn2 + h1 @ W2 + b2
    gemm_kernel<4,false><<<dim3(DE/128, SEQ/128), 256, SMEM_NT>>>(
        SEQ, DE, DMLP, h1, DMLP, 0, W2b, DE, 0, out, DE, 0,
        b2, 1.f, x2, xn2f);
}

// round 16
// speedup vs baseline: 1.2937x; 1.2104x over previous
#include <cuda_runtime.h>
#include <cuda_fp16.h>
#include <mma.h>
#include <cmath>
#include <cstdint>

using namespace nvcuda;
typedef __half hlf;

// Problem dims
constexpr int SEQ   = 2048;
constexpr int DE    = 2048;
constexpr int DMLP  = 8192;
constexpr int NH    = 16;

// Fused QKV layout (columns): [0,2048) q(h,e) | [2048,4096) k(h,e) |
// [4096,4111) v0 for heads 0..14 | 4111 pad | [4112,4240) v15 | pad to 4352
constexpr int NQKV   = 4352;
constexpr int VOFF0  = 4096;
constexpr int VOFF15 = 4112;
constexpr int YLD    = 160;   // ysmall padded K (143 real, rest zero)

// ---------------- device scratch (zero-initialized at module load) ----------
__device__ __align__(256) hlf   g_xn1h [SEQ*DE];
__device__ __align__(256) hlf   g_Bqkv [DE*NQKV];          // K-major [DE][NQKV]
__device__ __align__(256) float g_bqkv [NQKV];
__device__ __align__(256) hlf   g_qkv  [SEQ*NQKV];
__device__ __align__(256) hlf   g_Sh   [(size_t)NH*SEQ*SEQ];  // fp16 scores
__device__ __align__(256) hlf   g_P    [SEQ*SEQ];
__device__ __align__(256) hlf   g_ys   [SEQ*YLD];          // cols 143..159 zero
__device__ __align__(256) hlf   g_Woh  [YLD*DE];           // K-major, rows 143+ zero
__device__ __align__(256) float g_x2   [SEQ*DE];
__device__ __align__(256) hlf   g_xn2h [SEQ*DE];
__device__ __align__(256) float g_xn2f [SEQ*DE];
__device__ __align__(256) hlf   g_W1h  [(size_t)DE*DMLP];  // K-major
__device__ __align__(256) hlf   g_h1   [(size_t)SEQ*DMLP];
__device__ __align__(256) hlf   g_W2h  [(size_t)DMLP*DE];  // K-major

// ---------------- cp.async helpers ------------------------------------------
__device__ __forceinline__ void cp16(void* dst, const void* src) {
    unsigned d = (unsigned)__cvta_generic_to_shared(dst);
    asm volatile("cp.async.cg.shared.global [%0], [%1], 16;\n" :: "r"(d), "l"(src));
}
__device__ __forceinline__ void cp_commit() {
    asm volatile("cp.async.commit_group;\n");
}
template<int N> __device__ __forceinline__ void cp_wait() {
    asm volatile("cp.async.wait_group %0;\n" :: "n"(N));
}

// ---------------- WMMA fp16 GEMM (fp16 accumulate), 4-stage cp.async --------
// C(MxN) = epilogue( alpha * A(MxK) @ B + bias ), per-z batch offsets.
// TRANSB=0: B is K-major [K][N] (row_major frags). TRANSB=1: B is N-major
// [N][K] (col_major frags) => computes A @ B^T.
// Block 128x128, warp tile 64x32, 8 warps, 2 CTAs/SM, 1 sync per k-tile.
// MODE: 0 fp16 out (acc*alpha+bias) | 2 f32 out (2X+acc+bias)
//       3 fp16 out gelu(acc+bias)   | 4 f32 out (X+X2n+acc+bias)
template<int MODE, bool TRANSB>
__global__ __launch_bounds__(256, 2)
void gemm_kernel(int M, int N, int K,
                 const hlf* __restrict__ A, int lda, long aB,
                 const hlf* __restrict__ B, int ldb, long bB,
                 void* __restrict__ C, int ldc, long cB,
                 const float* __restrict__ bias, float alpha,
                 const float* __restrict__ X, const float* __restrict__ X2n)
{
    constexpr int ASZ   = 128 * 40;                    // 5120 elems
    constexpr int BSZ   = TRANSB ? 128 * 40 : 32 * 136;
    constexpr int STAGE = ASZ + BSZ;
    constexpr int BSTR  = TRANSB ? 40 : 136;           // B smem row stride

    extern __shared__ char smc[];
    hlf* base = (hlf*)smc;

    const int tid    = threadIdx.x;
    const int warpId = tid >> 5;
    const int lane   = tid & 31;
    const int wm     = warpId & 1;    // 2 warps along M
    const int wn     = warpId >> 1;   // 4 warps along N
    const int bm     = blockIdx.y * 128;
    const int bn     = blockIdx.x * 128;
    const int z      = blockIdx.z;

    const hlf* Ag = A + (size_t)z * aB;
    const hlf* Bg = B + (size_t)z * bB;
    const size_t cOff = (size_t)z * cB;

    // chunk maps (16B each; 2 per thread per operand tile)
    const int ar  = tid >> 2,         ac  = (tid & 3) * 8;
    const int ar2 = (tid + 256) >> 2, ac2 = ((tid + 256) & 3) * 8;
    const int br  = tid >> 4,         bc  = (tid & 15) * 8;
    const int br2 = (tid + 256) >> 4, bc2 = ((tid + 256) & 15) * 8;

    auto issue = [&](int kt, int s) {
        const int k0 = kt << 5;
        hlf* Asb = base + s * STAGE;
        hlf* Bsb = Asb + ASZ;
        cp16(Asb + ar  * 40 + ac,  Ag + (size_t)(bm + ar ) * lda + k0 + ac );
        cp16(Asb + ar2 * 40 + ac2, Ag + (size_t)(bm + ar2) * lda + k0 + ac2);
        if (TRANSB) {
            cp16(Bsb + ar  * 40 + ac,  Bg + (size_t)(bn + ar ) * ldb + k0 + ac );
            cp16(Bsb + ar2 * 40 + ac2, Bg + (size_t)(bn + ar2) * ldb + k0 + ac2);
        } else {
            cp16(Bsb + br  * 136 + bc,  Bg + (size_t)(k0 + br ) * ldb + bn + bc );
            cp16(Bsb + br2 * 136 + bc2, Bg + (size_t)(k0 + br2) * ldb + bn + bc2);
        }
        cp_commit();
    };

    wmma::fragment<wmma::accumulator,16,16,16,hlf> acc[4][2];
    #pragma unroll
    for (int i = 0; i < 4; i++)
        #pragma unroll
        for (int j = 0; j < 2; j++)
            wmma::fill_fragment(acc[i][j], __float2half(0.f));

    const int KT = K >> 5;
    #pragma unroll
    for (int i = 0; i < 3; i++) {
        if (i < KT) issue(i, i); else cp_commit();
    }

    for (int kt = 0; kt < KT; kt++) {
        cp_wait<2>();
        __syncthreads();
        if (kt + 3 < KT) issue(kt + 3, (kt + 3) & 3);
        else             cp_commit();   // keep group count constant

        const int s = kt & 3;
        const hlf* Asb = base + s * STAGE;
        const hlf* Bsb = Asb + ASZ;
        #pragma unroll
        for (int ks = 0; ks < 32; ks += 16) {
            wmma::fragment<wmma::matrix_a,16,16,16,hlf,wmma::row_major> af[4];
            #pragma unroll
            for (int i = 0; i < 4; i++)
                wmma::load_matrix_sync(af[i], Asb + (wm*64 + i*16)*40 + ks, 40);
            if (TRANSB) {
                wmma::fragment<wmma::matrix_b,16,16,16,hlf,wmma::col_major> bfr[2];
                #pragma unroll
                for (int j = 0; j < 2; j++)
                    wmma::load_matrix_sync(bfr[j], Bsb + (wn*32 + j*16)*BSTR + ks, BSTR);
                #pragma unroll
                for (int i = 0; i < 4; i++)
                    #pragma unroll
                    for (int j = 0; j < 2; j++)
                        wmma::mma_sync(acc[i][j], af[i], bfr[j], acc[i][j]);
            } else {
                wmma::fragment<wmma::matrix_b,16,16,16,hlf,wmma::row_major> bfr[2];
                #pragma unroll
                for (int j = 0; j < 2; j++)
                    wmma::load_matrix_sync(bfr[j], Bsb + ks*BSTR + wn*32 + j*16, BSTR);
                #pragma unroll
                for (int i = 0; i < 4; i++)
                    #pragma unroll
                    for (int j = 0; j < 2; j++)
                        wmma::mma_sync(acc[i][j], af[i], bfr[j], acc[i][j]);
            }
        }
    }
    __syncthreads();   // all warps done with smem; reuse front as epilogue stage

    hlf* stg = (hlf*)smc + warpId * 384;     // 16 x 24 halves per warp
    #pragma unroll
    for (int i = 0; i < 4; i++) {
        #pragma unroll
        for (int j = 0; j < 2; j++) {
            wmma::store_matrix_sync(stg, acc[i][j], 24, wmma::mem_row_major);
            __syncwarp();
            #pragma unroll
            for (int e = 0; e < 8; e++) {
                int el = lane*8 + e;
                int r = el >> 4, c = el & 15;
                float v = __half2float(stg[r*24 + c]) * alpha;
                int grow = bm + wm*64 + i*16 + r;
                int gcol = bn + wn*32 + j*16 + c;
                if (bias) v += bias[gcol];
                size_t idx = cOff + (size_t)grow * ldc + gcol;
                if constexpr (MODE == 0) {
                    ((hlf*)C)[idx] = __float2half(v);
                } else if constexpr (MODE == 2) {
                    ((float*)C)[idx] = 2.f * X[idx] + v;
                } else if constexpr (MODE == 3) {
                    float g = 0.5f * v *
                        (1.f + tanhf(0.7978845608028654f * (v + 0.044715f*v*v*v)));
                    ((hlf*)C)[idx] = __float2half(g);
                } else {
                    ((float*)C)[idx] = X[idx] + X2n[idx] + v;
                }
            }
            __syncwarp();
        }
    }
}

constexpr int SMEM_NT = 4 * (128*40 + 32*136) * 2;   // 75776 B (K-major B)
constexpr int SMEM_TR = 4 * (128*40 + 128*40) * 2;   // 81920 B (N-major B)

// ---------------- layernorm (population std) --------------------------------
template<bool WF>
__global__ __launch_bounds__(256)
void ln_kernel(const float* __restrict__ X, const float* __restrict__ gamma,
               const float* __restrict__ beta,
               hlf* __restrict__ ob, float* __restrict__ of)
{
    int row = blockIdx.x, tid = threadIdx.x;
    const float* xr = X + (size_t)row * DE;
    float v[8], s = 0.f, sq = 0.f;
    #pragma unroll
    for (int i = 0; i < 8; i++) {
        v[i] = xr[tid + i*256];
        s  += v[i];
        sq += v[i]*v[i];
    }
    __shared__ float r1[256], r2[256];
    r1[tid] = s; r2[tid] = sq; __syncthreads();
    for (int o = 128; o > 0; o >>= 1) {
        if (tid < o) { r1[tid] += r1[tid+o]; r2[tid] += r2[tid+o]; }
        __syncthreads();
    }
    float mean = r1[0] * (1.f/DE);
    float var  = r2[0] * (1.f/DE) - mean*mean;
    float sd   = sqrtf(fmaxf(var, 0.f));
    if (sd == 0.f) sd = 1.f;
    float rs = 1.f / sd;
    #pragma unroll
    for (int i = 0; i < 8; i++) {
        int d = tid + i*256;
        float y = gamma[d] * ((v[i] - mean) * rs) + beta[d];
        ob[(size_t)row*DE + d] = __float2half(y);
        if (WF) of[(size_t)row*DE + d] = y;
    }
}

// ---------------- batched softmax (fp16 scores) + per-head fold --------------
__global__ __launch_bounds__(256)
void softmax_kernel(const hlf* __restrict__ S, const hlf* __restrict__ qkv,
                    hlf* __restrict__ P, hlf* __restrict__ ys)
{
    int row = blockIdx.x, head = blockIdx.y, tid = threadIdx.x;
    const hlf* Sr = S + (size_t)head*SEQ*SEQ + (size_t)row*SEQ;
    float s[8];
    #pragma unroll
    for (int i = 0; i < 8; i++) s[i] = __half2float(Sr[tid + i*256]);
    float mx = s[0];
    #pragma unroll
    for (int i = 1; i < 8; i++) mx = fmaxf(mx, s[i]);
    __shared__ float red[256];
    red[tid] = mx; __syncthreads();
    for (int o = 128; o > 0; o >>= 1) {
        if (tid < o) red[tid] = fmaxf(red[tid], red[tid+o]);
        __syncthreads();
    }
    mx = red[0]; __syncthreads();

    float e[8], ls = 0.f;
    #pragma unroll
    for (int i = 0; i < 8; i++) { e[i] = expf(s[i] - mx); ls += e[i]; }
    red[tid] = ls; __syncthreads();
    for (int o = 128; o > 0; o >>= 1) {
        if (tid < o) red[tid] += red[tid+o];
        __syncthreads();
    }
    float tot = red[0]; __syncthreads();

    if (head == 15) {
        float inv = 1.f / tot;
        #pragma unroll
        for (int i = 0; i < 8; i++)
            P[(size_t)row*SEQ + tid + i*256] = __float2half(e[i] * inv);
    } else {
        float dot = 0.f;
        #pragma unroll
        for (int i = 0; i < 8; i++) {
            int m = tid + i*256;
            dot += e[i] * __half2float(qkv[(size_t)m*NQKV + VOFF0 + head]);
        }
        red[tid] = dot; __syncthreads();
        for (int o = 128; o > 0; o >>= 1) {
            if (tid < o) red[tid] += red[tid+o];
            __syncthreads();
        }
        if (tid == 0)
            ys[(size_t)row*YLD + head] = __float2half(red[0] / tot);
    }
}

// ---------------- weight packing --------------------------------------------
__global__ void pack_qkv_kernel(const float* __restrict__ Wq,
                                const float* __restrict__ Wk,
                                const float* __restrict__ Wv,
                                hlf* __restrict__ Bq)
{
    const size_t total = (size_t)DE * NQKV;
    for (size_t idx = (size_t)blockIdx.x*blockDim.x + threadIdx.x;
         idx < total; idx += (size_t)gridDim.x*blockDim.x) {
        int d = (int)(idx / NQKV);
        int n = (int)(idx % NQKV);
        float w = 0.f;
        if (n < 2048) {
            w = Wq[(size_t)(n >> 7)*DE*128 + (size_t)d*128 + (n & 127)];
        } else if (n < 4096) {
            int m = n - 2048;
            w = Wk[(size_t)(m >> 7)*DE*128 + (size_t)d*128 + (m & 127)];
        } else if (n < 4111) {
            w = Wv[(size_t)(n - 4096)*DE*128 + (size_t)d*128];
        } else if (n >= VOFF15 && n < VOFF15 + 128) {
            w = Wv[(size_t)15*DE*128 + (size_t)d*128 + (n - VOFF15)];
        }
        Bq[idx] = __float2half(w);
    }
}

__global__ void pack_bias_kernel(const float* __restrict__ bq,
                                 const float* __restrict__ bk,
                                 const float* __restrict__ bv,
                                 float* __restrict__ out)
{
    int n = blockIdx.x*blockDim.x + threadIdx.x;
    if (n >= NQKV) return;
    float b = 0.f;
    if (n < 2048)                           b = bq[n];
    else if (n < 4096)                      b = bk[n - 2048];
    else if (n < 4111)                      b = bv[(n - 4096)*128];
    else if (n >= VOFF15 && n < VOFF15+128) b = bv[15*128 + (n - VOFF15)];
    out[n] = b;
}

__global__ void pack_wo_kernel(const float* __restrict__ Wo, hlf* __restrict__ out)
{
    for (int idx = blockIdx.x*blockDim.x + threadIdx.x;
         idx < YLD*DE; idx += gridDim.x*blockDim.x) {
        int r = idx / DE;
        out[idx] = __float2half(r < 143 ? Wo[idx] : 0.f);
    }
}

// vectorized fp32 -> fp16 (4 elems per thread-iter)
__global__ void cvt_kernel(const float4* __restrict__ in, uint2* __restrict__ out,
                           size_t n4)
{
    for (size_t i = (size_t)blockIdx.x*blockDim.x + threadIdx.x;
         i < n4; i += (size_t)gridDim.x*blockDim.x) {
        float4 v = in[i];
        __half2 a = __floats2half2_rn(v.x, v.y);
        __half2 b = __floats2half2_rn(v.z, v.w);
        uint2 o;
        o.x = *(unsigned*)&a;
        o.y = *(unsigned*)&b;
        out[i] = o;
    }
}

// ---------------- host orchestration ----------------------------------------
extern "C" void kernel_launch(void* const* d_in, const int* in_sizes, int n_in,
                              void* d_out, int out_size)
{
    (void)in_sizes; (void)n_in; (void)out_size;
    const float* x   = (const float*)d_in[0];
    const float* Wq  = (const float*)d_in[1];
    const float* bq  = (const float*)d_in[2];
    const float* Wk  = (const float*)d_in[3];
    const float* bk  = (const float*)d_in[4];
    const float* Wv  = (const float*)d_in[5];
    const float* bv  = (const float*)d_in[6];
    const float* Wo  = (const float*)d_in[7];
    const float* bo  = (const float*)d_in[8];
    const float* g1  = (const float*)d_in[9];
    const float* be1 = (const float*)d_in[10];
    const float* g2  = (const float*)d_in[11];
    const float* be2 = (const float*)d_in[12];
    const float* W1  = (const float*)d_in[13];
    const float* b1  = (const float*)d_in[14];
    const float* W2  = (const float*)d_in[15];
    const float* b2  = (const float*)d_in[16];
    float* out = (float*)d_out;

    hlf *xn1h, *Bqkv, *qkv, *Sh, *P, *ys, *Woh, *xn2h, *W1h, *h1, *W2h;
    float *bqkv, *x2, *xn2f;
    cudaGetSymbolAddress((void**)&xn1h, g_xn1h);
    cudaGetSymbolAddress((void**)&Bqkv, g_Bqkv);
    cudaGetSymbolAddress((void**)&bqkv, g_bqkv);
    cudaGetSymbolAddress((void**)&qkv,  g_qkv);
    cudaGetSymbolAddress((void**)&Sh,   g_Sh);
    cudaGetSymbolAddress((void**)&P,    g_P);
    cudaGetSymbolAddress((void**)&ys,   g_ys);
    cudaGetSymbolAddress((void**)&Woh,  g_Woh);
    cudaGetSymbolAddress((void**)&x2,   g_x2);
    cudaGetSymbolAddress((void**)&xn2h, g_xn2h);
    cudaGetSymbolAddress((void**)&xn2f, g_xn2f);
    cudaGetSymbolAddress((void**)&W1h,  g_W1h);
    cudaGetSymbolAddress((void**)&h1,   g_h1);
    cudaGetSymbolAddress((void**)&W2h,  g_W2h);

    cudaFuncSetAttribute(gemm_kernel<0,false>,
        cudaFuncAttributeMaxDynamicSharedMemorySize, SMEM_NT);
    cudaFuncSetAttribute(gemm_kernel<0,true>,
        cudaFuncAttributeMaxDynamicSharedMemorySize, SMEM_TR);
    cudaFuncSetAttribute(gemm_kernel<2,false>,
        cudaFuncAttributeMaxDynamicSharedMemorySize, SMEM_NT);
    cudaFuncSetAttribute(gemm_kernel<3,false>,
        cudaFuncAttributeMaxDynamicSharedMemorySize, SMEM_NT);
    cudaFuncSetAttribute(gemm_kernel<4,false>,
        cudaFuncAttributeMaxDynamicSharedMemorySize, SMEM_NT);

    // Weight packing / conversion (K-major everywhere, fp16)
    pack_qkv_kernel <<<4096, 256>>>(Wq, Wk, Wv, Bqkv);
    pack_bias_kernel<<<(NQKV + 255)/256, 256>>>(bq, bk, bv, bqkv);
    pack_wo_kernel  <<<640, 256>>>(Wo, Woh);
    cvt_kernel      <<<4096, 256>>>((const float4*)W1, (uint2*)W1h,
                                    (size_t)DE * DMLP / 4);
    cvt_kernel      <<<4096, 256>>>((const float4*)W2, (uint2*)W2h,
                                    (size_t)DMLP * DE / 4);

    // LN1
    ln_kernel<false><<<SEQ, 256>>>(x, g1, be1, xn1h, nullptr);

    // Fused QKV: qkv = xn1 @ Wqkv + bias   (2048 x 4352, K=2048)
    gemm_kernel<0,false><<<dim3(NQKV/128, SEQ/128), 256, SMEM_NT>>>(
        SEQ, NQKV, DE, xn1h, DE, 0, Bqkv, NQKV, 0, qkv, NQKV, 0,
        bqkv, 1.f, nullptr, nullptr);

    // Batched scores: S[h] = q_h k_h^T / sqrt(128) -> fp16  (z = head)
    const float alphaS = 0.08838834764831845f;
    gemm_kernel<0,true><<<dim3(SEQ/128, SEQ/128, NH), 256, SMEM_TR>>>(
        SEQ, SEQ, 128, qkv, NQKV, 128, qkv + 2048, NQKV, 128,
        Sh, SEQ, (long)SEQ*SEQ, nullptr, alphaS, nullptr, nullptr);

    // Batched softmax: heads 0..14 fold to scalar, head 15 writes P
    softmax_kernel<<<dim3(SEQ, NH), 256>>>(Sh, qkv, P, ys);

    // Head 15 PV: P @ v15 -> ysmall cols [15,143)
    gemm_kernel<0,false><<<dim3(1, SEQ/128), 256, SMEM_NT>>>(
        SEQ, 128, SEQ, P, SEQ, 0, qkv + VOFF15, NQKV, 0,
        ys + 15, YLD, 0, nullptr, 1.f, nullptr, nullptr);

    // mh + residual: x2 = 2x + ysmall @ Wo_top + bo  (K padded to 160)
    gemm_kernel<2,false><<<dim3(DE/128, SEQ/128), 256, SMEM_NT>>>(
        SEQ, DE, YLD, ys, YLD, 0, Woh, DE, 0, x2, DE, 0,
        bo, 1.f, x, nullptr);

    // LN2
    ln_kernel<true><<<SEQ, 256>>>(x2, g2, be2, xn2h, xn2f);

    // MLP1: gelu(xn2 @ W1 + b1) -> fp16
    gemm_kernel<3,false><<<dim3(DMLP/128, SEQ/128), 256, SMEM_NT>>>(
        SEQ, DMLP, DE, xn2h, DE, 0, W1h, DMLP, 0, h1, DMLP, 0,
        b1, 1.f, nullptr, nullptr);

    // MLP2 + final residual: out = x2 + xn2 + h1 @ W2 + b2
    gemm_kernel<4,false><<<dim3(DE/128, SEQ/128), 256, SMEM_NT>>>(
        SEQ, DE, DMLP, h1, DMLP, 0, W2h, DE, 0, out, DE, 0,
        b2, 1.f, x2, xn2f);
}